// round 5
// baseline (speedup 1.0000x reference)
#include <cuda_runtime.h>
#include <cstdint>

#define NA 100000
#define NB 100000
#define NE 1600000
#define BF 128
#define AF 128

// ---------------------------------------------------------------------------
// Device scratch (allocation-free rule: device globals)
// ---------------------------------------------------------------------------
__device__ float g_support[(size_t)NB * AF];   // 51.2 MB  a_support
__device__ int   g_count[NA];                  // per-row edge counts / fill cursor
__device__ int   g_excl[NA];                   // block-local exclusive scan
__device__ int   g_start[NA + 1];              // CSR row starts
__device__ int   g_bsum[256];                  // per-scan-block sums
__device__ int   g_bscan[256];                 // scanned block sums
__device__ int   g_ecol[NE];                   // CSR-ordered cols
__device__ float g_eval[NE];                   // CSR-ordered vals

#define SCAN_BS 512
#define SCAN_NBLK ((NA + SCAN_BS - 1) / SCAN_BS)   // 196

// ---------------------------------------------------------------------------
// Packed dual-lane fp32 helpers (Blackwell f32x2 pipe)
// ---------------------------------------------------------------------------
__device__ __forceinline__ unsigned long long pack2(float x) {
    unsigned long long r;
    asm("mov.b64 %0, {%1, %1};" : "=l"(r) : "f"(x));
    return r;
}
__device__ __forceinline__ void fma2(unsigned long long& d,
                                     unsigned long long a,
                                     unsigned long long b) {
    asm("fma.rn.f32x2 %0, %1, %2, %0;" : "+l"(d) : "l"(a), "l"(b));
}

// ---------------------------------------------------------------------------
// Kernel 1: dense GEMM  g_support[NB,128] = B[NB,128] @ W[128,128]
// 256 threads, 128x128 tile, 8x8 per-thread register tile, FFMA2 inner loop.
// ---------------------------------------------------------------------------
#define TILE_M 128
#define KT 32

__global__ __launch_bounds__(256, 2) void gemm_kernel(const float* __restrict__ B,
                                                      const float* __restrict__ W) {
    __shared__ float BsT[KT][TILE_M];   // [k][row]
    __shared__ float Ws [KT][128];      // [k][col]

    const int tid = threadIdx.x;
    const int tx  = tid & 15;           // cols [tx*8, tx*8+8)
    const int ty  = tid >> 4;           // rows [ty*8, ty*8+8)
    const int row0 = blockIdx.x * TILE_M;

    // Accumulator: 8 rows x 4 col-pairs, packed f32x2
    unsigned long long accp[8][4];
    #pragma unroll
    for (int i = 0; i < 8; i++)
        #pragma unroll
        for (int j = 0; j < 4; j++) accp[i][j] = 0ull;

    for (int kt = 0; kt < BF; kt += KT) {
        // ---- Load B tile transposed into BsT[k][row]
        {
            const int r  = tid & 127;
            const int kq = (tid >> 7) * 16;
            const int gr = min(row0 + r, NB - 1);
            const float4* src = (const float4*)(B + (size_t)gr * BF + kt + kq);
            #pragma unroll
            for (int q = 0; q < 4; q++) {
                float4 v = src[q];
                int k = kq + q * 4;
                BsT[k + 0][r] = v.x;
                BsT[k + 1][r] = v.y;
                BsT[k + 2][r] = v.z;
                BsT[k + 3][r] = v.w;
            }
        }
        // ---- Load W tile (32 k x 128 cols)
        {
            #pragma unroll
            for (int q = 0; q < 4; q++) {
                int idx = tid + q * 256;
                int kk  = idx >> 5;
                int cc  = idx & 31;
                ((float4*)&Ws[kk][0])[cc] =
                    ((const float4*)(W + (size_t)(kt + kk) * AF))[cc];
            }
        }
        __syncthreads();

        #pragma unroll
        for (int k = 0; k < KT; k++) {
            // W operand: 8 consecutive floats = 4 f32x2 pairs (2x LDS.128)
            ulonglong2 wp0 = ((const ulonglong2*)&Ws[k][0])[tx * 2];
            ulonglong2 wp1 = ((const ulonglong2*)&Ws[k][0])[tx * 2 + 1];
            unsigned long long ww[4] = {wp0.x, wp0.y, wp1.x, wp1.y};
            // B operand: 8 row values (broadcast-heavy LDS, nearly free)
            float4 b0 = ((const float4*)&BsT[k][0])[ty * 2];
            float4 b1 = ((const float4*)&BsT[k][0])[ty * 2 + 1];
            float bb[8] = {b0.x, b0.y, b0.z, b0.w, b1.x, b1.y, b1.z, b1.w};
            #pragma unroll
            for (int i = 0; i < 8; i++) {
                unsigned long long bp = pack2(bb[i]);
                #pragma unroll
                for (int j = 0; j < 4; j++)
                    fma2(accp[i][j], bp, ww[j]);
            }
        }
        __syncthreads();
    }

    // ---- Store 8x8 tile (each pair = 2 floats, 2x16B per row)
    #pragma unroll
    for (int i = 0; i < 8; i++) {
        int gr = row0 + ty * 8 + i;
        if (gr < NB) {
            ulonglong2* dst = (ulonglong2*)(g_support + (size_t)gr * AF + tx * 8);
            dst[0] = make_ulonglong2(accp[i][0], accp[i][1]);
            dst[1] = make_ulonglong2(accp[i][2], accp[i][3]);
        }
    }
}

// ---------------------------------------------------------------------------
// CSR build
// ---------------------------------------------------------------------------
__global__ __launch_bounds__(256) void zero_counts_kernel() {
    int i = blockIdx.x * blockDim.x + threadIdx.x;
    if (i < NA) g_count[i] = 0;
}

__global__ __launch_bounds__(256) void hist_kernel(const int* __restrict__ rows) {
    int e = blockIdx.x * blockDim.x + threadIdx.x;
    if (e < NE) atomicAdd(&g_count[rows[e]], 1);
}

// Block-level inclusive scan of 512 counts; exclusive part -> g_excl, sum -> g_bsum
__global__ __launch_bounds__(SCAN_BS) void scan1_kernel() {
    __shared__ int sdata[SCAN_BS];
    const int t   = threadIdx.x;
    const int idx = blockIdx.x * SCAN_BS + t;
    int x = (idx < NA) ? g_count[idx] : 0;
    sdata[t] = x;
    __syncthreads();
    #pragma unroll
    for (int off = 1; off < SCAN_BS; off <<= 1) {
        int y = (t >= off) ? sdata[t - off] : 0;
        __syncthreads();
        sdata[t] += y;
        __syncthreads();
    }
    if (idx < NA) g_excl[idx] = sdata[t] - x;
    if (t == SCAN_BS - 1) g_bsum[blockIdx.x] = sdata[t];
}

// Single block: exclusive scan of the block sums
__global__ __launch_bounds__(256) void scan2_kernel() {
    __shared__ int s[SCAN_NBLK];
    int t = threadIdx.x;
    if (t < SCAN_NBLK) s[t] = g_bsum[t];
    __syncthreads();
    if (t == 0) {
        int run = 0;
        for (int i = 0; i < SCAN_NBLK; i++) {
            int v = s[i];
            s[i] = run;
            run += v;
        }
    }
    __syncthreads();
    if (t < SCAN_NBLK) g_bscan[t] = s[t];
}

__global__ __launch_bounds__(256) void scan3_kernel() {
    int i = blockIdx.x * blockDim.x + threadIdx.x;
    if (i < NA) g_start[i] = g_excl[i] + g_bscan[i / SCAN_BS];
    if (i == 0) g_start[NA] = NE;
}

// Place edges into CSR buckets. atomicSub drains g_count back to 0.
__global__ __launch_bounds__(256) void place_kernel(const int*   __restrict__ rows,
                                                    const int*   __restrict__ cols,
                                                    const float* __restrict__ vals) {
    int e = blockIdx.x * blockDim.x + threadIdx.x;
    if (e >= NE) return;
    int row = rows[e];
    int old = atomicSub(&g_count[row], 1);       // old in [1..cnt]
    int pos = g_start[row] + old - 1;
    g_ecol[pos] = cols[e];
    g_eval[pos] = vals[e];
}

// ---------------------------------------------------------------------------
// SpMM + bias: one warp per output row, single STG per out row.
// ---------------------------------------------------------------------------
__global__ __launch_bounds__(256) void spmm_kernel(const float* __restrict__ bias,
                                                   float*       __restrict__ out) {
    const int warp = (blockIdx.x * blockDim.x + threadIdx.x) >> 5;
    const int lane = threadIdx.x & 31;
    if (warp >= NA) return;

    const int s    = g_start[warp];
    const int eend = g_start[warp + 1];

    float4 acc = ((const float4*)bias)[lane];

    int e = s;
    for (; e + 4 <= eend; e += 4) {
        int   c0 = g_ecol[e],     c1 = g_ecol[e + 1];
        int   c2 = g_ecol[e + 2], c3 = g_ecol[e + 3];
        float v0 = g_eval[e],     v1 = g_eval[e + 1];
        float v2 = g_eval[e + 2], v3 = g_eval[e + 3];
        float4 x0 = __ldg((const float4*)(g_support + (size_t)c0 * AF) + lane);
        float4 x1 = __ldg((const float4*)(g_support + (size_t)c1 * AF) + lane);
        float4 x2 = __ldg((const float4*)(g_support + (size_t)c2 * AF) + lane);
        float4 x3 = __ldg((const float4*)(g_support + (size_t)c3 * AF) + lane);
        acc.x += v0 * x0.x; acc.y += v0 * x0.y; acc.z += v0 * x0.z; acc.w += v0 * x0.w;
        acc.x += v1 * x1.x; acc.y += v1 * x1.y; acc.z += v1 * x1.z; acc.w += v1 * x1.w;
        acc.x += v2 * x2.x; acc.y += v2 * x2.y; acc.z += v2 * x2.z; acc.w += v2 * x2.w;
        acc.x += v3 * x3.x; acc.y += v3 * x3.y; acc.z += v3 * x3.z; acc.w += v3 * x3.w;
    }
    for (; e < eend; e++) {
        int   c = g_ecol[e];
        float v = g_eval[e];
        float4 x = __ldg((const float4*)(g_support + (size_t)c * AF) + lane);
        acc.x += v * x.x; acc.y += v * x.y; acc.z += v * x.z; acc.w += v * x.w;
    }

    ((float4*)(out + (size_t)warp * AF))[lane] = acc;
}

// ---------------------------------------------------------------------------
// Launch
// inputs: b_input[NB*BF], edge_rows[NE], edge_cols[NE], edge_vals[NE],
//         a_weight[BF*AF], a_bias[AF];  output: [NA, AF] float32
// ---------------------------------------------------------------------------
extern "C" void kernel_launch(void* const* d_in, const int* in_sizes, int n_in,
                              void* d_out, int out_size) {
    const float* b_input   = (const float*)d_in[0];
    const int*   edge_rows = (const int*)  d_in[1];
    const int*   edge_cols = (const int*)  d_in[2];
    const float* edge_vals = (const float*)d_in[3];
    const float* a_weight  = (const float*)d_in[4];
    const float* a_bias    = (const float*)d_in[5];
    float*       out       = (float*)d_out;

    // 1) a_support = b_input @ a_weight  (FFMA2 inner loop)
    gemm_kernel<<<(NB + TILE_M - 1) / TILE_M, 256>>>(b_input, a_weight);

    // 2) CSR build from COO (independent of GEMM result)
    zero_counts_kernel<<<(NA + 255) / 256, 256>>>();
    hist_kernel<<<(NE + 255) / 256, 256>>>(edge_rows);
    scan1_kernel<<<SCAN_NBLK, SCAN_BS>>>();
    scan2_kernel<<<1, 256>>>();
    scan3_kernel<<<(NA + 255) / 256, 256>>>();
    place_kernel<<<(NE + 255) / 256, 256>>>(edge_rows, edge_cols, edge_vals);

    // 3) SpMM + bias, one warp per row, single STG per out row
    spmm_kernel<<<(NA * 32 + 255) / 256, 256>>>(a_bias, out);
}

// round 7
// speedup vs baseline: 1.6855x; 1.6855x over previous
#include <cuda_runtime.h>
#include <cuda_fp16.h>
#include <cstdint>

#define NA 100000
#define NB 100000
#define NE 1600000
#define BF 128
#define AF 128

// ---------------------------------------------------------------------------
// Device scratch (allocation-free rule: device globals)
// ---------------------------------------------------------------------------
__device__ __half g_support[(size_t)NB * AF];  // 25.6 MB  a_support (fp16)
__device__ int    g_count[NA];                 // per-row counts / fill cursor
__device__ int    g_excl[NA];                  // block-local exclusive scan
__device__ int    g_start[NA + 1];             // CSR row starts
__device__ int    g_bsum[256];                 // per-scan-block sums
__device__ int    g_bscan[256];                // scanned block sums
__device__ int    g_ecol[NE];                  // CSR-ordered cols
__device__ float  g_eval[NE];                  // CSR-ordered vals

#define SCAN_BS 512
#define SCAN_NBLK ((NA + SCAN_BS - 1) / SCAN_BS)   // 196

__device__ __forceinline__ unsigned int h2_bits(__half2 h) {
    return *reinterpret_cast<unsigned int*>(&h);
}

// ---------------------------------------------------------------------------
// Kernel 1: dense GEMM  g_support[NB,128] = fp16(B[NB,128] @ W[128,128])
// 256 threads, 128x128 tile, 8x8 per-thread register tile (proven scalar FFMA).
// ---------------------------------------------------------------------------
#define TILE_M 128
#define KT 32

__global__ __launch_bounds__(256, 2) void gemm_kernel(const float* __restrict__ B,
                                                      const float* __restrict__ W) {
    __shared__ float BsT[KT][TILE_M];   // [k][row]
    __shared__ float Ws [KT][128];      // [k][col]

    const int tid = threadIdx.x;
    const int tx  = tid & 15;           // cols [tx*8, tx*8+8)
    const int ty  = tid >> 4;           // rows [ty*8, ty*8+8)
    const int row0 = blockIdx.x * TILE_M;

    float acc[8][8];
    #pragma unroll
    for (int i = 0; i < 8; i++)
        #pragma unroll
        for (int j = 0; j < 8; j++) acc[i][j] = 0.0f;

    for (int kt = 0; kt < BF; kt += KT) {
        // ---- Load B tile transposed into BsT[k][row]
        {
            const int r  = tid & 127;
            const int kq = (tid >> 7) * 16;
            const int gr = min(row0 + r, NB - 1);
            const float4* src = (const float4*)(B + (size_t)gr * BF + kt + kq);
            #pragma unroll
            for (int q = 0; q < 4; q++) {
                float4 v = src[q];
                int k = kq + q * 4;
                BsT[k + 0][r] = v.x;
                BsT[k + 1][r] = v.y;
                BsT[k + 2][r] = v.z;
                BsT[k + 3][r] = v.w;
            }
        }
        // ---- Load W tile (32 k x 128 cols)
        {
            #pragma unroll
            for (int q = 0; q < 4; q++) {
                int idx = tid + q * 256;
                int kk  = idx >> 5;
                int cc  = idx & 31;
                ((float4*)&Ws[kk][0])[cc] =
                    ((const float4*)(W + (size_t)(kt + kk) * AF))[cc];
            }
        }
        __syncthreads();

        #pragma unroll
        for (int k = 0; k < KT; k++) {
            float4 b0 = ((const float4*)&BsT[k][0])[ty * 2];
            float4 b1 = ((const float4*)&BsT[k][0])[ty * 2 + 1];
            float4 w0 = ((const float4*)&Ws[k][0])[tx * 2];
            float4 w1 = ((const float4*)&Ws[k][0])[tx * 2 + 1];
            float bb[8] = {b0.x, b0.y, b0.z, b0.w, b1.x, b1.y, b1.z, b1.w};
            float ww[8] = {w0.x, w0.y, w0.z, w0.w, w1.x, w1.y, w1.z, w1.w};
            #pragma unroll
            for (int i = 0; i < 8; i++)
                #pragma unroll
                for (int j = 0; j < 8; j++)
                    acc[i][j] += bb[i] * ww[j];
        }
        __syncthreads();
    }

    // ---- Store 8x8 tile as fp16: 8 halves = 16B per row -> one STG.128
    #pragma unroll
    for (int i = 0; i < 8; i++) {
        int gr = row0 + ty * 8 + i;
        if (gr < NB) {
            uint4 pk;
            pk.x = h2_bits(__floats2half2_rn(acc[i][0], acc[i][1]));
            pk.y = h2_bits(__floats2half2_rn(acc[i][2], acc[i][3]));
            pk.z = h2_bits(__floats2half2_rn(acc[i][4], acc[i][5]));
            pk.w = h2_bits(__floats2half2_rn(acc[i][6], acc[i][7]));
            *(uint4*)(g_support + (size_t)gr * AF + tx * 8) = pk;
        }
    }
}

// ---------------------------------------------------------------------------
// CSR build (g_count starts at 0: zero-initialized globals + place_kernel's
// atomicSub drains it back to 0 on every invocation -> replay-safe)
// ---------------------------------------------------------------------------
__global__ __launch_bounds__(256) void hist_kernel(const int* __restrict__ rows) {
    int e = blockIdx.x * blockDim.x + threadIdx.x;
    if (e < NE) atomicAdd(&g_count[rows[e]], 1);
}

__global__ __launch_bounds__(SCAN_BS) void scan1_kernel() {
    __shared__ int sdata[SCAN_BS];
    const int t   = threadIdx.x;
    const int idx = blockIdx.x * SCAN_BS + t;
    int x = (idx < NA) ? g_count[idx] : 0;
    sdata[t] = x;
    __syncthreads();
    #pragma unroll
    for (int off = 1; off < SCAN_BS; off <<= 1) {
        int y = (t >= off) ? sdata[t - off] : 0;
        __syncthreads();
        sdata[t] += y;
        __syncthreads();
    }
    if (idx < NA) g_excl[idx] = sdata[t] - x;
    if (t == SCAN_BS - 1) g_bsum[blockIdx.x] = sdata[t];
}

__global__ __launch_bounds__(256) void scan2_kernel() {
    __shared__ int s[SCAN_NBLK];
    int t = threadIdx.x;
    if (t < SCAN_NBLK) s[t] = g_bsum[t];
    __syncthreads();
    if (t == 0) {
        int run = 0;
        for (int i = 0; i < SCAN_NBLK; i++) {
            int v = s[i];
            s[i] = run;
            run += v;
        }
    }
    __syncthreads();
    if (t < SCAN_NBLK) g_bscan[t] = s[t];
}

__global__ __launch_bounds__(256) void scan3_kernel() {
    int i = blockIdx.x * blockDim.x + threadIdx.x;
    if (i < NA) g_start[i] = g_excl[i] + g_bscan[i / SCAN_BS];
    if (i == 0) g_start[NA] = NE;
}

__global__ __launch_bounds__(256) void place_kernel(const int*   __restrict__ rows,
                                                    const int*   __restrict__ cols,
                                                    const float* __restrict__ vals) {
    int e = blockIdx.x * blockDim.x + threadIdx.x;
    if (e >= NE) return;
    int row = rows[e];
    int old = atomicSub(&g_count[row], 1);       // drains count back to 0
    int pos = g_start[row] + old - 1;
    g_ecol[pos] = cols[e];
    g_eval[pos] = vals[e];
}

// ---------------------------------------------------------------------------
// SpMM + bias: one warp per output row. fp16 gather (8B/lane), fp32 math,
// single fp32 STG per out row.
// ---------------------------------------------------------------------------
__global__ __launch_bounds__(256) void spmm_kernel(const float* __restrict__ bias,
                                                   float*       __restrict__ out) {
    const int warp = (blockIdx.x * blockDim.x + threadIdx.x) >> 5;
    const int lane = threadIdx.x & 31;
    if (warp >= NA) return;

    const int s    = g_start[warp];
    const int eend = g_start[warp + 1];

    float4 acc = ((const float4*)bias)[lane];

    int e = s;
    for (; e + 4 <= eend; e += 4) {
        int   c0 = g_ecol[e],     c1 = g_ecol[e + 1];
        int   c2 = g_ecol[e + 2], c3 = g_ecol[e + 3];
        float v0 = g_eval[e],     v1 = g_eval[e + 1];
        float v2 = g_eval[e + 2], v3 = g_eval[e + 3];
        uint2 p0 = __ldg((const uint2*)(g_support + (size_t)c0 * AF) + lane);
        uint2 p1 = __ldg((const uint2*)(g_support + (size_t)c1 * AF) + lane);
        uint2 p2 = __ldg((const uint2*)(g_support + (size_t)c2 * AF) + lane);
        uint2 p3 = __ldg((const uint2*)(g_support + (size_t)c3 * AF) + lane);
        {
            float2 a = __half22float2(*reinterpret_cast<__half2*>(&p0.x));
            float2 b = __half22float2(*reinterpret_cast<__half2*>(&p0.y));
            acc.x += v0 * a.x; acc.y += v0 * a.y; acc.z += v0 * b.x; acc.w += v0 * b.y;
        }
        {
            float2 a = __half22float2(*reinterpret_cast<__half2*>(&p1.x));
            float2 b = __half22float2(*reinterpret_cast<__half2*>(&p1.y));
            acc.x += v1 * a.x; acc.y += v1 * a.y; acc.z += v1 * b.x; acc.w += v1 * b.y;
        }
        {
            float2 a = __half22float2(*reinterpret_cast<__half2*>(&p2.x));
            float2 b = __half22float2(*reinterpret_cast<__half2*>(&p2.y));
            acc.x += v2 * a.x; acc.y += v2 * a.y; acc.z += v2 * b.x; acc.w += v2 * b.y;
        }
        {
            float2 a = __half22float2(*reinterpret_cast<__half2*>(&p3.x));
            float2 b = __half22float2(*reinterpret_cast<__half2*>(&p3.y));
            acc.x += v3 * a.x; acc.y += v3 * a.y; acc.z += v3 * b.x; acc.w += v3 * b.y;
        }
    }
    for (; e < eend; e++) {
        int   c = g_ecol[e];
        float v = g_eval[e];
        uint2 p = __ldg((const uint2*)(g_support + (size_t)c * AF) + lane);
        float2 a = __half22float2(*reinterpret_cast<__half2*>(&p.x));
        float2 b = __half22float2(*reinterpret_cast<__half2*>(&p.y));
        acc.x += v * a.x; acc.y += v * a.y; acc.z += v * b.x; acc.w += v * b.y;
    }

    ((float4*)(out + (size_t)warp * AF))[lane] = acc;
}

// ---------------------------------------------------------------------------
// Launch
// inputs: b_input[NB*BF], edge_rows[NE], edge_cols[NE], edge_vals[NE],
//         a_weight[BF*AF], a_bias[AF];  output: [NA, AF] float32
// ---------------------------------------------------------------------------
extern "C" void kernel_launch(void* const* d_in, const int* in_sizes, int n_in,
                              void* d_out, int out_size) {
    const float* b_input   = (const float*)d_in[0];
    const int*   edge_rows = (const int*)  d_in[1];
    const int*   edge_cols = (const int*)  d_in[2];
    const float* edge_vals = (const float*)d_in[3];
    const float* a_weight  = (const float*)d_in[4];
    const float* a_bias    = (const float*)d_in[5];
    float*       out       = (float*)d_out;

    // 1) a_support = fp16(b_input @ a_weight)
    gemm_kernel<<<(NB + TILE_M - 1) / TILE_M, 256>>>(b_input, a_weight);

    // 2) CSR build from COO
    hist_kernel<<<(NE + 255) / 256, 256>>>(edge_rows);
    scan1_kernel<<<SCAN_NBLK, SCAN_BS>>>();
    scan2_kernel<<<1, 256>>>();
    scan3_kernel<<<(NA + 255) / 256, 256>>>();
    place_kernel<<<(NE + 255) / 256, 256>>>(edge_rows, edge_cols, edge_vals);

    // 3) SpMM + bias
    spmm_kernel<<<(NA * 32 + 255) / 256, 256>>>(a_bias, out);
}

// round 8
// speedup vs baseline: 2.2646x; 1.3436x over previous
#include <cuda_runtime.h>
#include <cuda_fp16.h>
#include <cstdint>

#define NA 100000
#define NB 100000
#define NE 1600000
#define BF 128
#define AF 128

// ---------------------------------------------------------------------------
// Device scratch (allocation-free rule: device globals)
// ---------------------------------------------------------------------------
__device__ __half g_support[(size_t)NB * AF];  // 25.6 MB  a_support (fp16)
__device__ uint2  g_wpack[16 * 16 * 32];       // W in mma fragment order (64 KB)
__device__ int    g_count[NA];                 // per-row counts / fill cursor
__device__ int    g_excl[NA];                  // block-local exclusive scan
__device__ int    g_start[NA + 1];             // CSR row starts
__device__ int    g_bsum[256];                 // per-scan-block sums
__device__ int    g_ecol[NE];                  // CSR-ordered cols
__device__ float  g_eval[NE];                  // CSR-ordered vals

#define SCAN_BS 512
#define SCAN_NBLK ((NA + SCAN_BS - 1) / SCAN_BS)   // 196

__device__ __forceinline__ unsigned int h2_bits(__half2 h) {
    return *reinterpret_cast<unsigned int*>(&h);
}
__device__ __forceinline__ unsigned int f2tf32(float f) {
    unsigned int r;
    asm("cvt.rna.tf32.f32 %0, %1;" : "=r"(r) : "f"(f));
    return r;
}
__device__ __forceinline__ void mma_tf32(float acc[4], const unsigned int a[4],
                                         unsigned int b0, unsigned int b1) {
    asm("mma.sync.aligned.m16n8k8.row.col.f32.tf32.tf32.f32 "
        "{%0,%1,%2,%3}, {%4,%5,%6,%7}, {%8,%9}, {%0,%1,%2,%3};"
        : "+f"(acc[0]), "+f"(acc[1]), "+f"(acc[2]), "+f"(acc[3])
        : "r"(a[0]), "r"(a[1]), "r"(a[2]), "r"(a[3]), "r"(b0), "r"(b1));
}

// ---------------------------------------------------------------------------
// Kernel 0: pack W[128,128] into mma b-fragment order (tf32 bit patterns).
// Index: [q (k-chunk 0..15)][j (n-tile 0..15)][lane] -> uint2{b0, b1}
//   b0 = W[q*8 + lane%4    ][j*8 + lane/4]
//   b1 = W[q*8 + lane%4 + 4][j*8 + lane/4]
// ---------------------------------------------------------------------------
__global__ __launch_bounds__(256) void pack_w_kernel(const float* __restrict__ W) {
    int idx = blockIdx.x * blockDim.x + threadIdx.x;
    if (idx >= 16 * 16 * 32) return;
    int lane = idx & 31;
    int j    = (idx >> 5) & 15;
    int q    = idx >> 9;
    int k0 = q * 8 + (lane & 3);
    int n  = j * 8 + (lane >> 2);
    uint2 p;
    p.x = f2tf32(W[(size_t)k0 * AF + n]);
    p.y = f2tf32(W[(size_t)(k0 + 4) * AF + n]);
    g_wpack[idx] = p;
}

// ---------------------------------------------------------------------------
// Kernel 1: tensor-core GEMM  g_support = fp16(B @ W), tf32 mma.sync.
// Block 256 = 8 warps; tile 128 rows x 128 cols; warp = 32 rows x 64 cols.
// A fragments straight from GMEM (rows are block-exclusive), B from g_wpack.
// ---------------------------------------------------------------------------
__global__ __launch_bounds__(256, 2) void gemm_kernel(const float* __restrict__ B) {
    const int tid  = threadIdx.x;
    const int warp = tid >> 5;
    const int lane = tid & 31;
    const int g    = lane >> 2;       // group id 0..7
    const int t    = lane & 3;        // thread-in-group 0..3
    const int wr   = warp >> 1;       // warp row group 0..3
    const int wc   = warp & 1;        // warp col group 0..1
    const int R0   = blockIdx.x * 128 + wr * 32;
    const int JB   = wc * 8;          // first n-tile (of 16)

    float acc[2][8][4];
    #pragma unroll
    for (int rt = 0; rt < 2; rt++)
        #pragma unroll
        for (int j = 0; j < 8; j++)
            #pragma unroll
            for (int c = 0; c < 4; c++) acc[rt][j][c] = 0.0f;

    // Clamped global row indices for the two 16-row mma tiles
    int rA0 = min(R0 + g,      NB - 1);
    int rA1 = min(R0 + g + 8,  NB - 1);
    int rA2 = min(R0 + 16 + g, NB - 1);
    int rA3 = min(R0 + 24 + g, NB - 1);

    for (int q = 0; q < 16; q++) {
        const int k0 = q * 8 + t;
        // ---- A fragments (tf32), 8 scalar LDG
        unsigned int a0[4], a1[4];
        a0[0] = f2tf32(__ldg(B + (size_t)rA0 * BF + k0));
        a0[1] = f2tf32(__ldg(B + (size_t)rA1 * BF + k0));
        a0[2] = f2tf32(__ldg(B + (size_t)rA0 * BF + k0 + 4));
        a0[3] = f2tf32(__ldg(B + (size_t)rA1 * BF + k0 + 4));
        a1[0] = f2tf32(__ldg(B + (size_t)rA2 * BF + k0));
        a1[1] = f2tf32(__ldg(B + (size_t)rA3 * BF + k0));
        a1[2] = f2tf32(__ldg(B + (size_t)rA2 * BF + k0 + 4));
        a1[3] = f2tf32(__ldg(B + (size_t)rA3 * BF + k0 + 4));
        // ---- B fragments: 8 coalesced LDG.64 (L1/L2 resident, 64 KB total)
        uint2 bf[8];
        #pragma unroll
        for (int j = 0; j < 8; j++)
            bf[j] = __ldg(&g_wpack[((q * 16) + JB + j) * 32 + lane]);
        // ---- 16 mma
        #pragma unroll
        for (int j = 0; j < 8; j++) {
            mma_tf32(acc[0][j], a0, bf[j].x, bf[j].y);
            mma_tf32(acc[1][j], a1, bf[j].x, bf[j].y);
        }
    }

    // ---- Epilogue: fp16 store. c0,c1 -> row r, cols n,n+1; c2,c3 -> row r+8.
    #pragma unroll
    for (int rt = 0; rt < 2; rt++) {
        int r_lo = R0 + rt * 16 + g;
        int r_hi = r_lo + 8;
        #pragma unroll
        for (int j = 0; j < 8; j++) {
            int n = (JB + j) * 8 + t * 2;
            if (r_lo < NB) {
                __half2 h = __floats2half2_rn(acc[rt][j][0], acc[rt][j][1]);
                *(unsigned int*)(g_support + (size_t)r_lo * AF + n) = h2_bits(h);
            }
            if (r_hi < NB) {
                __half2 h = __floats2half2_rn(acc[rt][j][2], acc[rt][j][3]);
                *(unsigned int*)(g_support + (size_t)r_hi * AF + n) = h2_bits(h);
            }
        }
    }
}

// ---------------------------------------------------------------------------
// CSR build (g_count starts at 0: zero-init globals + place_kernel's atomicSub
// drains it back to 0 every invocation -> replay-safe)
// ---------------------------------------------------------------------------
__global__ __launch_bounds__(256) void hist_kernel(const int* __restrict__ rows) {
    int e = blockIdx.x * blockDim.x + threadIdx.x;
    if (e < NE) atomicAdd(&g_count[rows[e]], 1);
}

__global__ __launch_bounds__(SCAN_BS) void scan1_kernel() {
    __shared__ int sdata[SCAN_BS];
    const int t   = threadIdx.x;
    const int idx = blockIdx.x * SCAN_BS + t;
    int x = (idx < NA) ? g_count[idx] : 0;
    sdata[t] = x;
    __syncthreads();
    #pragma unroll
    for (int off = 1; off < SCAN_BS; off <<= 1) {
        int y = (t >= off) ? sdata[t - off] : 0;
        __syncthreads();
        sdata[t] += y;
        __syncthreads();
    }
    if (idx < NA) g_excl[idx] = sdata[t] - x;
    if (t == SCAN_BS - 1) g_bsum[blockIdx.x] = sdata[t];
}

// scan3 with folded-in prefix of block sums (eliminates the scan2 launch):
// block b reduces g_bsum[0..b) itself, then writes g_start for its chunk.
__global__ __launch_bounds__(SCAN_BS) void scan3_kernel() {
    __shared__ int red[SCAN_BS];
    const int b = blockIdx.x;
    const int t = threadIdx.x;
    red[t] = (t < b) ? g_bsum[t] : 0;    // b <= 195 < 512
    __syncthreads();
    #pragma unroll
    for (int off = SCAN_BS / 2; off > 0; off >>= 1) {
        if (t < off) red[t] += red[t + off];
        __syncthreads();
    }
    const int base = red[0];
    const int i = b * SCAN_BS + t;
    if (i < NA) g_start[i] = g_excl[i] + base;
    if (i == 0) g_start[NA] = NE;
}

__global__ __launch_bounds__(256) void place_kernel(const int*   __restrict__ rows,
                                                    const int*   __restrict__ cols,
                                                    const float* __restrict__ vals) {
    int e = blockIdx.x * blockDim.x + threadIdx.x;
    if (e >= NE) return;
    int row = rows[e];
    int old = atomicSub(&g_count[row], 1);       // drains count back to 0
    int pos = g_start[row] + old - 1;
    g_ecol[pos] = cols[e];
    g_eval[pos] = vals[e];
}

// ---------------------------------------------------------------------------
// SpMM + bias: one warp per output row. fp16 gather (8B/lane), fp32 math,
// single fp32 STG per out row.
// ---------------------------------------------------------------------------
__global__ __launch_bounds__(256) void spmm_kernel(const float* __restrict__ bias,
                                                   float*       __restrict__ out) {
    const int warp = (blockIdx.x * blockDim.x + threadIdx.x) >> 5;
    const int lane = threadIdx.x & 31;
    if (warp >= NA) return;

    const int s    = g_start[warp];
    const int eend = g_start[warp + 1];

    float4 acc = ((const float4*)bias)[lane];

    int e = s;
    for (; e + 4 <= eend; e += 4) {
        int   c0 = g_ecol[e],     c1 = g_ecol[e + 1];
        int   c2 = g_ecol[e + 2], c3 = g_ecol[e + 3];
        float v0 = g_eval[e],     v1 = g_eval[e + 1];
        float v2 = g_eval[e + 2], v3 = g_eval[e + 3];
        uint2 p0 = __ldg((const uint2*)(g_support + (size_t)c0 * AF) + lane);
        uint2 p1 = __ldg((const uint2*)(g_support + (size_t)c1 * AF) + lane);
        uint2 p2 = __ldg((const uint2*)(g_support + (size_t)c2 * AF) + lane);
        uint2 p3 = __ldg((const uint2*)(g_support + (size_t)c3 * AF) + lane);
        {
            float2 a = __half22float2(*reinterpret_cast<__half2*>(&p0.x));
            float2 b = __half22float2(*reinterpret_cast<__half2*>(&p0.y));
            acc.x += v0 * a.x; acc.y += v0 * a.y; acc.z += v0 * b.x; acc.w += v0 * b.y;
        }
        {
            float2 a = __half22float2(*reinterpret_cast<__half2*>(&p1.x));
            float2 b = __half22float2(*reinterpret_cast<__half2*>(&p1.y));
            acc.x += v1 * a.x; acc.y += v1 * a.y; acc.z += v1 * b.x; acc.w += v1 * b.y;
        }
        {
            float2 a = __half22float2(*reinterpret_cast<__half2*>(&p2.x));
            float2 b = __half22float2(*reinterpret_cast<__half2*>(&p2.y));
            acc.x += v2 * a.x; acc.y += v2 * a.y; acc.z += v2 * b.x; acc.w += v2 * b.y;
        }
        {
            float2 a = __half22float2(*reinterpret_cast<__half2*>(&p3.x));
            float2 b = __half22float2(*reinterpret_cast<__half2*>(&p3.y));
            acc.x += v3 * a.x; acc.y += v3 * a.y; acc.z += v3 * b.x; acc.w += v3 * b.y;
        }
    }
    for (; e < eend; e++) {
        int   c = g_ecol[e];
        float v = g_eval[e];
        uint2 p = __ldg((const uint2*)(g_support + (size_t)c * AF) + lane);
        float2 a = __half22float2(*reinterpret_cast<__half2*>(&p.x));
        float2 b = __half22float2(*reinterpret_cast<__half2*>(&p.y));
        acc.x += v * a.x; acc.y += v * a.y; acc.z += v * b.x; acc.w += v * b.y;
    }

    ((float4*)(out + (size_t)warp * AF))[lane] = acc;
}

// ---------------------------------------------------------------------------
// Launch
// inputs: b_input[NB*BF], edge_rows[NE], edge_cols[NE], edge_vals[NE],
//         a_weight[BF*AF], a_bias[AF];  output: [NA, AF] float32
// ---------------------------------------------------------------------------
extern "C" void kernel_launch(void* const* d_in, const int* in_sizes, int n_in,
                              void* d_out, int out_size) {
    const float* b_input   = (const float*)d_in[0];
    const int*   edge_rows = (const int*)  d_in[1];
    const int*   edge_cols = (const int*)  d_in[2];
    const float* edge_vals = (const float*)d_in[3];
    const float* a_weight  = (const float*)d_in[4];
    const float* a_bias    = (const float*)d_in[5];
    float*       out       = (float*)d_out;

    // 1) W -> mma fragment order, then a_support = fp16(b_input @ W) via tf32 mma
    pack_w_kernel<<<(16 * 16 * 32 + 255) / 256, 256>>>(a_weight);
    gemm_kernel<<<(NB + 127) / 128, 256>>>(b_input);

    // 2) CSR build from COO
    hist_kernel<<<(NE + 255) / 256, 256>>>(edge_rows);
    scan1_kernel<<<SCAN_NBLK, SCAN_BS>>>();
    scan3_kernel<<<SCAN_NBLK, SCAN_BS>>>();
    place_kernel<<<(NE + 255) / 256, 256>>>(edge_rows, edge_cols, edge_vals);

    // 3) SpMM + bias
    spmm_kernel<<<(NA * 32 + 255) / 256, 256>>>(a_bias, out);
}

// round 9
// speedup vs baseline: 2.4314x; 1.0737x over previous
#include <cuda_runtime.h>
#include <cuda_fp16.h>
#include <cstdint>

#define NA 100000
#define NB 100000
#define NE 1600000
#define BF 128
#define AF 128

// ---------------------------------------------------------------------------
// Device scratch (allocation-free rule: device globals)
// ---------------------------------------------------------------------------
__device__ __half g_support[(size_t)NB * AF];  // 25.6 MB  a_support (fp16)
__device__ uint2  g_wpack[16 * 16 * 32];       // W in mma fragment order (64 KB)
__device__ int    g_count[NA];                 // per-row counts / fill cursor
__device__ int    g_excl[NA];                  // block-local exclusive scan
__device__ int    g_start[NA + 1];             // CSR row starts
__device__ int    g_bsum[256];                 // per-scan-block sums
__device__ int2   g_edge[NE];                  // CSR-ordered {col, val bits}

#define SCAN_BS 512
#define SCAN_NBLK ((NA + SCAN_BS - 1) / SCAN_BS)   // 196

__device__ __forceinline__ unsigned int h2_bits(__half2 h) {
    return *reinterpret_cast<unsigned int*>(&h);
}
__device__ __forceinline__ unsigned int f2tf32(float f) {
    unsigned int r;
    asm("cvt.rna.tf32.f32 %0, %1;" : "=r"(r) : "f"(f));
    return r;
}
__device__ __forceinline__ void mma_tf32(float acc[4], const unsigned int a[4],
                                         unsigned int b0, unsigned int b1) {
    asm("mma.sync.aligned.m16n8k8.row.col.f32.tf32.tf32.f32 "
        "{%0,%1,%2,%3}, {%4,%5,%6,%7}, {%8,%9}, {%0,%1,%2,%3};"
        : "+f"(acc[0]), "+f"(acc[1]), "+f"(acc[2]), "+f"(acc[3])
        : "r"(a[0]), "r"(a[1]), "r"(a[2]), "r"(a[3]), "r"(b0), "r"(b1));
}

// ---------------------------------------------------------------------------
// Kernel 0: pack W[128,128] into mma b-fragment order (tf32 bit patterns).
//   b0 = W[q*8 + lane%4    ][j*8 + lane/4]
//   b1 = W[q*8 + lane%4 + 4][j*8 + lane/4]
// ---------------------------------------------------------------------------
__global__ __launch_bounds__(256) void pack_w_kernel(const float* __restrict__ W) {
    int idx = blockIdx.x * blockDim.x + threadIdx.x;
    if (idx >= 16 * 16 * 32) return;
    int lane = idx & 31;
    int j    = (idx >> 5) & 15;
    int q    = idx >> 9;
    int k0 = q * 8 + (lane & 3);
    int n  = j * 8 + (lane >> 2);
    uint2 p;
    p.x = f2tf32(W[(size_t)k0 * AF + n]);
    p.y = f2tf32(W[(size_t)(k0 + 4) * AF + n]);
    g_wpack[idx] = p;
}

// ---------------------------------------------------------------------------
// Kernel 1: tensor-core GEMM  g_support = fp16(B @ W), tf32 mma.sync.
// 256 threads = 8 warps; block tile 128 rows x 128 cols; warp = 32 x 64.
// A staged per 16-k phase through smem (coalesced float4 loads, each byte
// read once); fragments via conflict-free pad-20 LDS. B frags from g_wpack.
// ---------------------------------------------------------------------------
#define APAD 20   // (20*g + t) % 32 covers all banks -> conflict-free

__global__ __launch_bounds__(256, 2) void gemm_kernel(const float* __restrict__ B) {
    __shared__ float As[128][APAD];   // 16 k-cols (+4 pad), 10 KB

    const int tid  = threadIdx.x;
    const int warp = tid >> 5;
    const int lane = tid & 31;
    const int g    = lane >> 2;       // group id 0..7
    const int t    = lane & 3;        // thread-in-group 0..3
    const int wr   = warp >> 1;       // warp row group 0..3
    const int wc   = warp & 1;        // warp col group 0..1
    const int row0 = blockIdx.x * 128;
    const int JB   = wc * 8;          // first n-tile (of 16)
    const int ra   = wr * 32 + g;     // smem base row for this thread's frags

    float acc[2][8][4];
    #pragma unroll
    for (int rt = 0; rt < 2; rt++)
        #pragma unroll
        for (int j = 0; j < 8; j++)
            #pragma unroll
            for (int c = 0; c < 4; c++) acc[rt][j][c] = 0.0f;

    // Precompute this thread's two coalesced A-load slots (row, c4)
    const int l_row0 = tid >> 2,          l_c4_0 = tid & 3;
    const int l_row1 = (tid + 256) >> 2,  l_c4_1 = (tid + 256) & 3;
    const int l_gr0  = min(row0 + l_row0, NB - 1);
    const int l_gr1  = min(row0 + l_row1, NB - 1);

    for (int ph = 0; ph < 8; ph++) {           // 16 k per phase
        const int kb = ph * 16;
        __syncthreads();                        // prior compute done
        // ---- Stage A[128 rows][16 k]: 512 float4, 2 per thread, coalesced
        {
            float4 v0 = *(const float4*)(B + (size_t)l_gr0 * BF + kb + l_c4_0 * 4);
            float4 v1 = *(const float4*)(B + (size_t)l_gr1 * BF + kb + l_c4_1 * 4);
            *(float4*)&As[l_row0][l_c4_0 * 4] = v0;
            *(float4*)&As[l_row1][l_c4_1 * 4] = v1;
        }
        __syncthreads();

        #pragma unroll
        for (int qq = 0; qq < 2; qq++) {
            const int q  = ph * 2 + qq;        // global k-chunk 0..15
            const int k0 = qq * 8 + t;
            unsigned int a0[4], a1[4];
            a0[0] = f2tf32(As[ra     ][k0]);
            a0[1] = f2tf32(As[ra +  8][k0]);
            a0[2] = f2tf32(As[ra     ][k0 + 4]);
            a0[3] = f2tf32(As[ra +  8][k0 + 4]);
            a1[0] = f2tf32(As[ra + 16][k0]);
            a1[1] = f2tf32(As[ra + 24][k0]);
            a1[2] = f2tf32(As[ra + 16][k0 + 4]);
            a1[3] = f2tf32(As[ra + 24][k0 + 4]);

            uint2 bf[8];
            #pragma unroll
            for (int j = 0; j < 8; j++)
                bf[j] = __ldg(&g_wpack[((q * 16) + JB + j) * 32 + lane]);

            #pragma unroll
            for (int j = 0; j < 8; j++) {
                mma_tf32(acc[0][j], a0, bf[j].x, bf[j].y);
                mma_tf32(acc[1][j], a1, bf[j].x, bf[j].y);
            }
        }
    }

    // ---- Epilogue: fp16 store. c0,c1 -> row r cols n,n+1; c2,c3 -> row r+8.
    const int R0 = row0 + wr * 32;
    #pragma unroll
    for (int rt = 0; rt < 2; rt++) {
        int r_lo = R0 + rt * 16 + g;
        int r_hi = r_lo + 8;
        #pragma unroll
        for (int j = 0; j < 8; j++) {
            int n = (JB + j) * 8 + t * 2;
            if (r_lo < NB) {
                __half2 h = __floats2half2_rn(acc[rt][j][0], acc[rt][j][1]);
                *(unsigned int*)(g_support + (size_t)r_lo * AF + n) = h2_bits(h);
            }
            if (r_hi < NB) {
                __half2 h = __floats2half2_rn(acc[rt][j][2], acc[rt][j][3]);
                *(unsigned int*)(g_support + (size_t)r_hi * AF + n) = h2_bits(h);
            }
        }
    }
}

// ---------------------------------------------------------------------------
// CSR build (g_count starts 0: zero-init globals + place's atomicSub drains
// it back to 0 every invocation -> replay-safe)
// ---------------------------------------------------------------------------
__global__ __launch_bounds__(256) void hist_kernel(const int* __restrict__ rows) {
    int e = blockIdx.x * blockDim.x + threadIdx.x;
    if (e < NE) atomicAdd(&g_count[rows[e]], 1);
}

__global__ __launch_bounds__(SCAN_BS) void scan1_kernel() {
    __shared__ int sdata[SCAN_BS];
    const int t   = threadIdx.x;
    const int idx = blockIdx.x * SCAN_BS + t;
    int x = (idx < NA) ? g_count[idx] : 0;
    sdata[t] = x;
    __syncthreads();
    #pragma unroll
    for (int off = 1; off < SCAN_BS; off <<= 1) {
        int y = (t >= off) ? sdata[t - off] : 0;
        __syncthreads();
        sdata[t] += y;
        __syncthreads();
    }
    if (idx < NA) g_excl[idx] = sdata[t] - x;
    if (t == SCAN_BS - 1) g_bsum[blockIdx.x] = sdata[t];
}

// Folded prefix-of-block-sums + start write (no separate scan2 launch)
__global__ __launch_bounds__(SCAN_BS) void scan3_kernel() {
    __shared__ int red[SCAN_BS];
    const int b = blockIdx.x;
    const int t = threadIdx.x;
    red[t] = (t < b) ? g_bsum[t] : 0;    // b <= 195 < 512
    __syncthreads();
    #pragma unroll
    for (int off = SCAN_BS / 2; off > 0; off >>= 1) {
        if (t < off) red[t] += red[t + off];
        __syncthreads();
    }
    const int base = red[0];
    const int i = b * SCAN_BS + t;
    if (i < NA) g_start[i] = g_excl[i] + base;
    if (i == 0) g_start[NA] = NE;
}

__global__ __launch_bounds__(256) void place_kernel(const int*   __restrict__ rows,
                                                    const int*   __restrict__ cols,
                                                    const float* __restrict__ vals) {
    int e = blockIdx.x * blockDim.x + threadIdx.x;
    if (e >= NE) return;
    int row = rows[e];
    int old = atomicSub(&g_count[row], 1);       // drains count back to 0
    int pos = g_start[row] + old - 1;
    int2 p;
    p.x = cols[e];
    p.y = __float_as_int(vals[e]);
    g_edge[pos] = p;                              // one 8B scattered store
}

// ---------------------------------------------------------------------------
// SpMM + bias: one warp per output row. fp16 gather (8B/lane), fp32 math,
// single fp32 STG per out row.
// ---------------------------------------------------------------------------
__global__ __launch_bounds__(256) void spmm_kernel(const float* __restrict__ bias,
                                                   float*       __restrict__ out) {
    const int warp = (blockIdx.x * blockDim.x + threadIdx.x) >> 5;
    const int lane = threadIdx.x & 31;
    if (warp >= NA) return;

    const int s    = g_start[warp];
    const int eend = g_start[warp + 1];

    float4 acc = ((const float4*)bias)[lane];

    int e = s;
    for (; e + 4 <= eend; e += 4) {
        int2 e0 = g_edge[e],     e1 = g_edge[e + 1];
        int2 e2 = g_edge[e + 2], e3 = g_edge[e + 3];
        float v0 = __int_as_float(e0.y), v1 = __int_as_float(e1.y);
        float v2 = __int_as_float(e2.y), v3 = __int_as_float(e3.y);
        uint2 p0 = __ldg((const uint2*)(g_support + (size_t)e0.x * AF) + lane);
        uint2 p1 = __ldg((const uint2*)(g_support + (size_t)e1.x * AF) + lane);
        uint2 p2 = __ldg((const uint2*)(g_support + (size_t)e2.x * AF) + lane);
        uint2 p3 = __ldg((const uint2*)(g_support + (size_t)e3.x * AF) + lane);
        {
            float2 a = __half22float2(*reinterpret_cast<__half2*>(&p0.x));
            float2 b = __half22float2(*reinterpret_cast<__half2*>(&p0.y));
            acc.x += v0 * a.x; acc.y += v0 * a.y; acc.z += v0 * b.x; acc.w += v0 * b.y;
        }
        {
            float2 a = __half22float2(*reinterpret_cast<__half2*>(&p1.x));
            float2 b = __half22float2(*reinterpret_cast<__half2*>(&p1.y));
            acc.x += v1 * a.x; acc.y += v1 * a.y; acc.z += v1 * b.x; acc.w += v1 * b.y;
        }
        {
            float2 a = __half22float2(*reinterpret_cast<__half2*>(&p2.x));
            float2 b = __half22float2(*reinterpret_cast<__half2*>(&p2.y));
            acc.x += v2 * a.x; acc.y += v2 * a.y; acc.z += v2 * b.x; acc.w += v2 * b.y;
        }
        {
            float2 a = __half22float2(*reinterpret_cast<__half2*>(&p3.x));
            float2 b = __half22float2(*reinterpret_cast<__half2*>(&p3.y));
            acc.x += v3 * a.x; acc.y += v3 * a.y; acc.z += v3 * b.x; acc.w += v3 * b.y;
        }
    }
    for (; e < eend; e++) {
        int2 ed = g_edge[e];
        float v = __int_as_float(ed.y);
        uint2 p = __ldg((const uint2*)(g_support + (size_t)ed.x * AF) + lane);
        float2 a = __half22float2(*reinterpret_cast<__half2*>(&p.x));
        float2 b = __half22float2(*reinterpret_cast<__half2*>(&p.y));
        acc.x += v * a.x; acc.y += v * a.y; acc.z += v * b.x; acc.w += v * b.y;
    }

    ((float4*)(out + (size_t)warp * AF))[lane] = acc;
}

// ---------------------------------------------------------------------------
// Launch
// inputs: b_input[NB*BF], edge_rows[NE], edge_cols[NE], edge_vals[NE],
//         a_weight[BF*AF], a_bias[AF];  output: [NA, AF] float32
// ---------------------------------------------------------------------------
extern "C" void kernel_launch(void* const* d_in, const int* in_sizes, int n_in,
                              void* d_out, int out_size) {
    const float* b_input   = (const float*)d_in[0];
    const int*   edge_rows = (const int*)  d_in[1];
    const int*   edge_cols = (const int*)  d_in[2];
    const float* edge_vals = (const float*)d_in[3];
    const float* a_weight  = (const float*)d_in[4];
    const float* a_bias    = (const float*)d_in[5];
    float*       out       = (float*)d_out;

    // 1) W -> mma fragment order, then a_support = fp16(b_input @ W) via tf32 mma
    pack_w_kernel<<<(16 * 16 * 32 + 255) / 256, 256>>>(a_weight);
    gemm_kernel<<<(NB + 127) / 128, 256>>>(b_input);

    // 2) CSR build from COO
    hist_kernel<<<(NE + 255) / 256, 256>>>(edge_rows);
    scan1_kernel<<<SCAN_NBLK, SCAN_BS>>>();
    scan3_kernel<<<SCAN_NBLK, SCAN_BS>>>();
    place_kernel<<<(NE + 255) / 256, 256>>>(edge_rows, edge_cols, edge_vals);

    // 3) SpMM + bias
    spmm_kernel<<<(NA * 32 + 255) / 256, 256>>>(a_bias, out);
}

// round 10
// speedup vs baseline: 2.4945x; 1.0260x over previous
#include <cuda_runtime.h>
#include <cuda_fp16.h>
#include <cstdint>

#define NA 100000
#define NB 100000
#define NE 1600000
#define BF 128
#define AF 128

// ---------------------------------------------------------------------------
// Device scratch (allocation-free rule: device globals)
// ---------------------------------------------------------------------------
__device__ __half g_support[(size_t)NB * AF];  // 25.6 MB  a_support (fp16)
__device__ uint2  g_wpack[16 * 16 * 32];       // W in mma fragment order (64 KB)
__device__ int    g_count[NA];                 // per-row counts / fill cursor
__device__ int    g_excl[NA];                  // block-local exclusive scan
__device__ int    g_start[NA + 1];             // CSR row starts
__device__ int    g_bsum[256];                 // per-scan-block sums
__device__ int2   g_edge[NE];                  // CSR-ordered {col, val bits}

#define SCAN_BS 512
#define SCAN_NBLK ((NA + SCAN_BS - 1) / SCAN_BS)   // 196

#define GEMM_BLOCKS ((NB + 127) / 128)             // 782
#define GEMM_THREADS (GEMM_BLOCKS * 256)           // 200192

__device__ __forceinline__ unsigned int h2_bits(__half2 h) {
    return *reinterpret_cast<unsigned int*>(&h);
}
__device__ __forceinline__ unsigned int f2tf32(float f) {
    unsigned int r;
    asm("cvt.rna.tf32.f32 %0, %1;" : "=r"(r) : "f"(f));
    return r;
}
__device__ __forceinline__ void mma_tf32(float acc[4], const unsigned int a[4],
                                         unsigned int b0, unsigned int b1) {
    asm("mma.sync.aligned.m16n8k8.row.col.f32.tf32.tf32.f32 "
        "{%0,%1,%2,%3}, {%4,%5,%6,%7}, {%8,%9}, {%0,%1,%2,%3};"
        : "+f"(acc[0]), "+f"(acc[1]), "+f"(acc[2]), "+f"(acc[3])
        : "r"(a[0]), "r"(a[1]), "r"(a[2]), "r"(a[3]), "r"(b0), "r"(b1));
}

// ---------------------------------------------------------------------------
// Kernel 0: pack W[128,128] into mma b-fragment order (tf32 bit patterns).
// ---------------------------------------------------------------------------
__global__ __launch_bounds__(256) void pack_w_kernel(const float* __restrict__ W) {
    int idx = blockIdx.x * blockDim.x + threadIdx.x;
    if (idx >= 16 * 16 * 32) return;
    int lane = idx & 31;
    int j    = (idx >> 5) & 15;
    int q    = idx >> 9;
    int k0 = q * 8 + (lane & 3);
    int n  = j * 8 + (lane >> 2);
    uint2 p;
    p.x = f2tf32(W[(size_t)k0 * AF + n]);
    p.y = f2tf32(W[(size_t)(k0 + 4) * AF + n]);
    g_wpack[idx] = p;
}

// ---------------------------------------------------------------------------
// Kernel 1: tensor-core GEMM  g_support = fp16(B @ W), tf32 mma.sync.
// + fused edge-row histogram in the prologue (independent work, hidden in
//   the GEMM's memory shadow; kernel boundary orders it before scan1).
// A staged per 16-k phase through double-buffered smem, PRE-CONVERTED to
// tf32 bits at staging. Pad-20 layout -> conflict-free LDS.
// ---------------------------------------------------------------------------
#define APAD 20

__global__ __launch_bounds__(256, 2) void gemm_kernel(const float* __restrict__ B,
                                                      const int* __restrict__ erows) {
    __shared__ unsigned int As[2][128][APAD];   // 2 x 10 KB, tf32 bits

    const int tid  = threadIdx.x;

    // ---- Fused histogram: 8 coalesced edge reads + spread L2 atomics
    {
        int gt = blockIdx.x * 256 + tid;
        #pragma unroll
        for (int i = 0; i < 8; i++) {
            int e = gt + i * GEMM_THREADS;
            if (e < NE) atomicAdd(&g_count[erows[e]], 1);
        }
    }

    const int warp = tid >> 5;
    const int lane = tid & 31;
    const int g    = lane >> 2;
    const int t    = lane & 3;
    const int wr   = warp >> 1;
    const int wc   = warp & 1;
    const int row0 = blockIdx.x * 128;
    const int JB   = wc * 8;
    const int ra   = wr * 32 + g;

    float acc[2][8][4];
    #pragma unroll
    for (int rt = 0; rt < 2; rt++)
        #pragma unroll
        for (int j = 0; j < 8; j++)
            #pragma unroll
            for (int c = 0; c < 4; c++) acc[rt][j][c] = 0.0f;

    // Two coalesced A-load slots per thread (row, float4-col)
    const int l_row0 = tid >> 2,       l_c4_0 = tid & 3;
    const int l_row1 = l_row0 + 64,    l_c4_1 = l_c4_0;
    const int l_gr0  = min(row0 + l_row0, NB - 1);
    const int l_gr1  = min(row0 + l_row1, NB - 1);

    // Stage phase kb into buffer buf, converting to tf32 bits
    auto stage = [&](int buf, int kb) {
        float4 v0 = *(const float4*)(B + (size_t)l_gr0 * BF + kb + l_c4_0 * 4);
        float4 v1 = *(const float4*)(B + (size_t)l_gr1 * BF + kb + l_c4_1 * 4);
        unsigned int* d0 = &As[buf][l_row0][l_c4_0 * 4];
        unsigned int* d1 = &As[buf][l_row1][l_c4_1 * 4];
        d0[0] = f2tf32(v0.x); d0[1] = f2tf32(v0.y);
        d0[2] = f2tf32(v0.z); d0[3] = f2tf32(v0.w);
        d1[0] = f2tf32(v1.x); d1[1] = f2tf32(v1.y);
        d1[2] = f2tf32(v1.z); d1[3] = f2tf32(v1.w);
    };

    stage(0, 0);
    __syncthreads();

    for (int ph = 0; ph < 8; ph++) {
        const int buf = ph & 1;
        if (ph < 7) stage(buf ^ 1, (ph + 1) * 16);   // prefetch next phase

        #pragma unroll
        for (int qq = 0; qq < 2; qq++) {
            const int q  = ph * 2 + qq;
            const int k0 = qq * 8 + t;
            unsigned int a0[4], a1[4];
            a0[0] = As[buf][ra     ][k0];
            a0[1] = As[buf][ra +  8][k0];
            a0[2] = As[buf][ra     ][k0 + 4];
            a0[3] = As[buf][ra +  8][k0 + 4];
            a1[0] = As[buf][ra + 16][k0];
            a1[1] = As[buf][ra + 24][k0];
            a1[2] = As[buf][ra + 16][k0 + 4];
            a1[3] = As[buf][ra + 24][k0 + 4];

            uint2 bf[8];
            #pragma unroll
            for (int j = 0; j < 8; j++)
                bf[j] = __ldg(&g_wpack[((q * 16) + JB + j) * 32 + lane]);

            #pragma unroll
            for (int j = 0; j < 8; j++) {
                mma_tf32(acc[0][j], a0, bf[j].x, bf[j].y);
                mma_tf32(acc[1][j], a1, bf[j].x, bf[j].y);
            }
        }
        __syncthreads();   // next phase's compute buffer is now fully staged
    }

    // ---- Epilogue: fp16 store
    const int R0 = row0 + wr * 32;
    #pragma unroll
    for (int rt = 0; rt < 2; rt++) {
        int r_lo = R0 + rt * 16 + g;
        int r_hi = r_lo + 8;
        #pragma unroll
        for (int j = 0; j < 8; j++) {
            int n = (JB + j) * 8 + t * 2;
            if (r_lo < NB) {
                __half2 h = __floats2half2_rn(acc[rt][j][0], acc[rt][j][1]);
                *(unsigned int*)(g_support + (size_t)r_lo * AF + n) = h2_bits(h);
            }
            if (r_hi < NB) {
                __half2 h = __floats2half2_rn(acc[rt][j][2], acc[rt][j][3]);
                *(unsigned int*)(g_support + (size_t)r_hi * AF + n) = h2_bits(h);
            }
        }
    }
}

// ---------------------------------------------------------------------------
// CSR build. (hist is fused into gemm_kernel. g_count drains back to 0 via
// place_kernel's atomicSub -> replay-safe.)
// ---------------------------------------------------------------------------
__global__ __launch_bounds__(SCAN_BS) void scan1_kernel() {
    __shared__ int wsum[16];
    const int t    = threadIdx.x;
    const int lane = t & 31;
    const int wid  = t >> 5;
    const int idx  = blockIdx.x * SCAN_BS + t;
    int x = (idx < NA) ? g_count[idx] : 0;

    // warp inclusive scan
    int v = x;
    #pragma unroll
    for (int off = 1; off < 32; off <<= 1) {
        int y = __shfl_up_sync(0xffffffffu, v, off);
        if (lane >= off) v += y;
    }
    if (lane == 31) wsum[wid] = v;
    __syncthreads();
    if (t < 16) {
        int s = wsum[t];
        #pragma unroll
        for (int off = 1; off < 16; off <<= 1) {
            int y = __shfl_up_sync(0x0000ffffu, s, off);
            if (t >= off) s += y;
        }
        wsum[t] = s;
    }
    __syncthreads();
    int incl = v + (wid ? wsum[wid - 1] : 0);
    if (idx < NA) g_excl[idx] = incl - x;
    if (t == SCAN_BS - 1) g_bsum[blockIdx.x] = incl;
}

// Prefix of block sums via shfl reduction + start write (no scan2 launch)
__global__ __launch_bounds__(SCAN_BS) void scan3_kernel() {
    __shared__ int ws[16];
    const int b    = blockIdx.x;
    const int t    = threadIdx.x;
    const int lane = t & 31;
    const int wid  = t >> 5;

    int v = (t < b) ? g_bsum[t] : 0;       // b <= 195 < 512
    #pragma unroll
    for (int off = 16; off > 0; off >>= 1)
        v += __shfl_down_sync(0xffffffffu, v, off);
    if (lane == 0) ws[wid] = v;
    __syncthreads();
    if (t < 16) {
        int s = ws[t];
        #pragma unroll
        for (int off = 8; off > 0; off >>= 1)
            s += __shfl_down_sync(0x0000ffffu, s, off);
        if (t == 0) ws[0] = s;
    }
    __syncthreads();
    const int base = ws[0];
    const int i = b * SCAN_BS + t;
    if (i < NA) g_start[i] = g_excl[i] + base;
    if (i == 0) g_start[NA] = NE;
}

__global__ __launch_bounds__(256) void place_kernel(const int*   __restrict__ rows,
                                                    const int*   __restrict__ cols,
                                                    const float* __restrict__ vals) {
    int e = blockIdx.x * blockDim.x + threadIdx.x;
    if (e >= NE) return;
    int row = rows[e];
    int old = atomicSub(&g_count[row], 1);       // drains count back to 0
    int pos = g_start[row] + old - 1;
    int2 p;
    p.x = cols[e];
    p.y = __float_as_int(vals[e]);
    g_edge[pos] = p;
}

// ---------------------------------------------------------------------------
// SpMM + bias: one warp per output row. fp16 gather (8B/lane), fp32 math,
// single fp32 STG per out row.
// ---------------------------------------------------------------------------
__global__ __launch_bounds__(256) void spmm_kernel(const float* __restrict__ bias,
                                                   float*       __restrict__ out) {
    const int warp = (blockIdx.x * blockDim.x + threadIdx.x) >> 5;
    const int lane = threadIdx.x & 31;
    if (warp >= NA) return;

    const int s    = g_start[warp];
    const int eend = g_start[warp + 1];

    float4 acc = ((const float4*)bias)[lane];

    int e = s;
    for (; e + 4 <= eend; e += 4) {
        int2 e0 = g_edge[e],     e1 = g_edge[e + 1];
        int2 e2 = g_edge[e + 2], e3 = g_edge[e + 3];
        float v0 = __int_as_float(e0.y), v1 = __int_as_float(e1.y);
        float v2 = __int_as_float(e2.y), v3 = __int_as_float(e3.y);
        uint2 p0 = __ldg((const uint2*)(g_support + (size_t)e0.x * AF) + lane);
        uint2 p1 = __ldg((const uint2*)(g_support + (size_t)e1.x * AF) + lane);
        uint2 p2 = __ldg((const uint2*)(g_support + (size_t)e2.x * AF) + lane);
        uint2 p3 = __ldg((const uint2*)(g_support + (size_t)e3.x * AF) + lane);
        {
            float2 a = __half22float2(*reinterpret_cast<__half2*>(&p0.x));
            float2 b = __half22float2(*reinterpret_cast<__half2*>(&p0.y));
            acc.x += v0 * a.x; acc.y += v0 * a.y; acc.z += v0 * b.x; acc.w += v0 * b.y;
        }
        {
            float2 a = __half22float2(*reinterpret_cast<__half2*>(&p1.x));
            float2 b = __half22float2(*reinterpret_cast<__half2*>(&p1.y));
            acc.x += v1 * a.x; acc.y += v1 * a.y; acc.z += v1 * b.x; acc.w += v1 * b.y;
        }
        {
            float2 a = __half22float2(*reinterpret_cast<__half2*>(&p2.x));
            float2 b = __half22float2(*reinterpret_cast<__half2*>(&p2.y));
            acc.x += v2 * a.x; acc.y += v2 * a.y; acc.z += v2 * b.x; acc.w += v2 * b.y;
        }
        {
            float2 a = __half22float2(*reinterpret_cast<__half2*>(&p3.x));
            float2 b = __half22float2(*reinterpret_cast<__half2*>(&p3.y));
            acc.x += v3 * a.x; acc.y += v3 * a.y; acc.z += v3 * b.x; acc.w += v3 * b.y;
        }
    }
    for (; e < eend; e++) {
        int2 ed = g_edge[e];
        float v = __int_as_float(ed.y);
        uint2 p = __ldg((const uint2*)(g_support + (size_t)ed.x * AF) + lane);
        float2 a = __half22float2(*reinterpret_cast<__half2*>(&p.x));
        float2 b = __half22float2(*reinterpret_cast<__half2*>(&p.y));
        acc.x += v * a.x; acc.y += v * a.y; acc.z += v * b.x; acc.w += v * b.y;
    }

    ((float4*)(out + (size_t)warp * AF))[lane] = acc;
}

// ---------------------------------------------------------------------------
// Launch
// inputs: b_input[NB*BF], edge_rows[NE], edge_cols[NE], edge_vals[NE],
//         a_weight[BF*AF], a_bias[AF];  output: [NA, AF] float32
// ---------------------------------------------------------------------------
extern "C" void kernel_launch(void* const* d_in, const int* in_sizes, int n_in,
                              void* d_out, int out_size) {
    const float* b_input   = (const float*)d_in[0];
    const int*   edge_rows = (const int*)  d_in[1];
    const int*   edge_cols = (const int*)  d_in[2];
    const float* edge_vals = (const float*)d_in[3];
    const float* a_weight  = (const float*)d_in[4];
    const float* a_bias    = (const float*)d_in[5];
    float*       out       = (float*)d_out;

    // 1) W pack, then GEMM (+fused edge-row histogram)
    pack_w_kernel<<<(16 * 16 * 32 + 255) / 256, 256>>>(a_weight);
    gemm_kernel<<<GEMM_BLOCKS, 256>>>(b_input, edge_rows);

    // 2) CSR scan + place
    scan1_kernel<<<SCAN_NBLK, SCAN_BS>>>();
    scan3_kernel<<<SCAN_NBLK, SCAN_BS>>>();
    place_kernel<<<(NE + 255) / 256, 256>>>(edge_rows, edge_cols, edge_vals);

    // 3) SpMM + bias
    spmm_kernel<<<(NA * 32 + 255) / 256, 256>>>(a_bias, out);
}

// round 12
// speedup vs baseline: 2.7138x; 1.0879x over previous
#include <cuda_runtime.h>
#include <cuda_fp16.h>
#include <cstdint>

#define NA 100000
#define NB 100000
#define NE 1600000
#define BF 128
#define AF 128

// ---------------------------------------------------------------------------
// Device scratch (allocation-free rule: device globals)
// ---------------------------------------------------------------------------
__device__ __half g_support[(size_t)NB * AF];  // 25.6 MB  a_support (fp16)
__device__ uint2  g_wpack[16 * 16 * 32];       // W in mma fragment order (64 KB)
__device__ int    g_count[NA];                 // per-row counts / fill cursor
__device__ int    g_excl[NA];                  // block-local exclusive scan
__device__ int    g_start[NA + 1];             // CSR row starts
__device__ int    g_bsum[256];                 // per-scan-block sums
__device__ int2   g_edge[NE];                  // CSR-ordered {col, val bits}

#define SCAN_BS 512
#define SCAN_NBLK ((NA + SCAN_BS - 1) / SCAN_BS)   // 196

__device__ __forceinline__ unsigned int h2_bits(__half2 h) {
    return *reinterpret_cast<unsigned int*>(&h);
}
__device__ __forceinline__ unsigned int f2tf32(float f) {
    unsigned int r;
    asm("cvt.rna.tf32.f32 %0, %1;" : "=r"(r) : "f"(f));
    return r;
}
__device__ __forceinline__ void mma_tf32(float acc[4], const unsigned int a[4],
                                         unsigned int b0, unsigned int b1) {
    asm("mma.sync.aligned.m16n8k8.row.col.f32.tf32.tf32.f32 "
        "{%0,%1,%2,%3}, {%4,%5,%6,%7}, {%8,%9}, {%0,%1,%2,%3};"
        : "+f"(acc[0]), "+f"(acc[1]), "+f"(acc[2]), "+f"(acc[3])
        : "r"(a[0]), "r"(a[1]), "r"(a[2]), "r"(a[3]), "r"(b0), "r"(b1));
}

// ---------------------------------------------------------------------------
// Kernel 0: pack W[128,128] into mma b-fragment order (tf32 bit patterns).
// ---------------------------------------------------------------------------
__global__ __launch_bounds__(256) void pack_w_kernel(const float* __restrict__ W) {
    int idx = blockIdx.x * blockDim.x + threadIdx.x;
    if (idx >= 16 * 16 * 32) return;
    int lane = idx & 31;
    int j    = (idx >> 5) & 15;
    int q    = idx >> 9;
    int k0 = q * 8 + (lane & 3);
    int n  = j * 8 + (lane >> 2);
    uint2 p;
    p.x = f2tf32(W[(size_t)k0 * AF + n]);
    p.y = f2tf32(W[(size_t)(k0 + 4) * AF + n]);
    g_wpack[idx] = p;
}

// ---------------------------------------------------------------------------
// Kernel 1: tensor-core GEMM  g_support = fp16(B @ W), tf32 mma.sync.
// A staged per 16-k phase through double-buffered smem, pre-converted to
// tf32 bits at staging. Pad-20 layout -> conflict-free LDS. (hist unfused.)
// ---------------------------------------------------------------------------
#define APAD 20

__global__ __launch_bounds__(256, 2) void gemm_kernel(const float* __restrict__ B) {
    __shared__ unsigned int As[2][128][APAD];   // 2 x 10 KB, tf32 bits

    const int tid  = threadIdx.x;
    const int warp = tid >> 5;
    const int lane = tid & 31;
    const int g    = lane >> 2;
    const int t    = lane & 3;
    const int wr   = warp >> 1;
    const int wc   = warp & 1;
    const int row0 = blockIdx.x * 128;
    const int JB   = wc * 8;
    const int ra   = wr * 32 + g;

    float acc[2][8][4];
    #pragma unroll
    for (int rt = 0; rt < 2; rt++)
        #pragma unroll
        for (int j = 0; j < 8; j++)
            #pragma unroll
            for (int c = 0; c < 4; c++) acc[rt][j][c] = 0.0f;

    const int l_row0 = tid >> 2,       l_c4_0 = tid & 3;
    const int l_row1 = l_row0 + 64,    l_c4_1 = l_c4_0;
    const int l_gr0  = min(row0 + l_row0, NB - 1);
    const int l_gr1  = min(row0 + l_row1, NB - 1);

    auto stage = [&](int buf, int kb) {
        float4 v0 = *(const float4*)(B + (size_t)l_gr0 * BF + kb + l_c4_0 * 4);
        float4 v1 = *(const float4*)(B + (size_t)l_gr1 * BF + kb + l_c4_1 * 4);
        unsigned int* d0 = &As[buf][l_row0][l_c4_0 * 4];
        unsigned int* d1 = &As[buf][l_row1][l_c4_1 * 4];
        d0[0] = f2tf32(v0.x); d0[1] = f2tf32(v0.y);
        d0[2] = f2tf32(v0.z); d0[3] = f2tf32(v0.w);
        d1[0] = f2tf32(v1.x); d1[1] = f2tf32(v1.y);
        d1[2] = f2tf32(v1.z); d1[3] = f2tf32(v1.w);
    };

    stage(0, 0);
    __syncthreads();

    for (int ph = 0; ph < 8; ph++) {
        const int buf = ph & 1;
        if (ph < 7) stage(buf ^ 1, (ph + 1) * 16);   // prefetch next phase

        #pragma unroll
        for (int qq = 0; qq < 2; qq++) {
            const int q  = ph * 2 + qq;
            const int k0 = qq * 8 + t;
            unsigned int a0[4], a1[4];
            a0[0] = As[buf][ra     ][k0];
            a0[1] = As[buf][ra +  8][k0];
            a0[2] = As[buf][ra     ][k0 + 4];
            a0[3] = As[buf][ra +  8][k0 + 4];
            a1[0] = As[buf][ra + 16][k0];
            a1[1] = As[buf][ra + 24][k0];
            a1[2] = As[buf][ra + 16][k0 + 4];
            a1[3] = As[buf][ra + 24][k0 + 4];

            uint2 bf[8];
            #pragma unroll
            for (int j = 0; j < 8; j++)
                bf[j] = __ldg(&g_wpack[((q * 16) + JB + j) * 32 + lane]);

            #pragma unroll
            for (int j = 0; j < 8; j++) {
                mma_tf32(acc[0][j], a0, bf[j].x, bf[j].y);
                mma_tf32(acc[1][j], a1, bf[j].x, bf[j].y);
            }
        }
        __syncthreads();
    }

    const int R0 = row0 + wr * 32;
    #pragma unroll
    for (int rt = 0; rt < 2; rt++) {
        int r_lo = R0 + rt * 16 + g;
        int r_hi = r_lo + 8;
        #pragma unroll
        for (int j = 0; j < 8; j++) {
            int n = (JB + j) * 8 + t * 2;
            if (r_lo < NB) {
                __half2 h = __floats2half2_rn(acc[rt][j][0], acc[rt][j][1]);
                *(unsigned int*)(g_support + (size_t)r_lo * AF + n) = h2_bits(h);
            }
            if (r_hi < NB) {
                __half2 h = __floats2half2_rn(acc[rt][j][2], acc[rt][j][3]);
                *(unsigned int*)(g_support + (size_t)r_hi * AF + n) = h2_bits(h);
            }
        }
    }
}

// ---------------------------------------------------------------------------
// CSR build chain (runs on the side stream, concurrent with the GEMM).
// g_count drains back to 0 via place_kernel's atomicSub -> replay-safe.
// ---------------------------------------------------------------------------
__global__ __launch_bounds__(256) void hist_kernel(const int* __restrict__ rows) {
    int e = blockIdx.x * blockDim.x + threadIdx.x;
    if (e < NE) atomicAdd(&g_count[rows[e]], 1);
}

__global__ __launch_bounds__(SCAN_BS) void scan1_kernel() {
    __shared__ int wsum[16];
    const int t    = threadIdx.x;
    const int lane = t & 31;
    const int wid  = t >> 5;
    const int idx  = blockIdx.x * SCAN_BS + t;
    int x = (idx < NA) ? g_count[idx] : 0;

    int v = x;
    #pragma unroll
    for (int off = 1; off < 32; off <<= 1) {
        int y = __shfl_up_sync(0xffffffffu, v, off);
        if (lane >= off) v += y;
    }
    if (lane == 31) wsum[wid] = v;
    __syncthreads();
    if (t < 16) {
        int s = wsum[t];
        #pragma unroll
        for (int off = 1; off < 16; off <<= 1) {
            int y = __shfl_up_sync(0x0000ffffu, s, off);
            if (t >= off) s += y;
        }
        wsum[t] = s;
    }
    __syncthreads();
    int incl = v + (wid ? wsum[wid - 1] : 0);
    if (idx < NA) g_excl[idx] = incl - x;
    if (t == SCAN_BS - 1) g_bsum[blockIdx.x] = incl;
}

__global__ __launch_bounds__(SCAN_BS) void scan3_kernel() {
    __shared__ int ws[16];
    const int b    = blockIdx.x;
    const int t    = threadIdx.x;
    const int lane = t & 31;
    const int wid  = t >> 5;

    int v = (t < b) ? g_bsum[t] : 0;       // b <= 195 < 512
    #pragma unroll
    for (int off = 16; off > 0; off >>= 1)
        v += __shfl_down_sync(0xffffffffu, v, off);
    if (lane == 0) ws[wid] = v;
    __syncthreads();
    if (t < 16) {
        int s = ws[t];
        #pragma unroll
        for (int off = 8; off > 0; off >>= 1)
            s += __shfl_down_sync(0x0000ffffu, s, off);
        if (t == 0) ws[0] = s;
    }
    __syncthreads();
    const int base = ws[0];
    const int i = b * SCAN_BS + t;
    if (i < NA) g_start[i] = g_excl[i] + base;
    if (i == 0) g_start[NA] = NE;
}

__global__ __launch_bounds__(256) void place_kernel(const int*   __restrict__ rows,
                                                    const int*   __restrict__ cols,
                                                    const float* __restrict__ vals) {
    int e = blockIdx.x * blockDim.x + threadIdx.x;
    if (e >= NE) return;
    int row = rows[e];
    int old = atomicSub(&g_count[row], 1);       // drains count back to 0
    int pos = g_start[row] + old - 1;
    int2 p;
    p.x = cols[e];
    p.y = __float_as_int(vals[e]);
    g_edge[pos] = p;
}

// ---------------------------------------------------------------------------
// SpMM + bias: one warp per output row. fp16 gather (8B/lane), fp32 math,
// single fp32 STG per out row.
// ---------------------------------------------------------------------------
__global__ __launch_bounds__(256) void spmm_kernel(const float* __restrict__ bias,
                                                   float*       __restrict__ out) {
    const int warp = (blockIdx.x * blockDim.x + threadIdx.x) >> 5;
    const int lane = threadIdx.x & 31;
    if (warp >= NA) return;

    const int s    = g_start[warp];
    const int eend = g_start[warp + 1];

    float4 acc = ((const float4*)bias)[lane];

    int e = s;
    for (; e + 4 <= eend; e += 4) {
        int2 e0 = g_edge[e],     e1 = g_edge[e + 1];
        int2 e2 = g_edge[e + 2], e3 = g_edge[e + 3];
        float v0 = __int_as_float(e0.y), v1 = __int_as_float(e1.y);
        float v2 = __int_as_float(e2.y), v3 = __int_as_float(e3.y);
        uint2 p0 = __ldg((const uint2*)(g_support + (size_t)e0.x * AF) + lane);
        uint2 p1 = __ldg((const uint2*)(g_support + (size_t)e1.x * AF) + lane);
        uint2 p2 = __ldg((const uint2*)(g_support + (size_t)e2.x * AF) + lane);
        uint2 p3 = __ldg((const uint2*)(g_support + (size_t)e3.x * AF) + lane);
        {
            float2 a = __half22float2(*reinterpret_cast<__half2*>(&p0.x));
            float2 b = __half22float2(*reinterpret_cast<__half2*>(&p0.y));
            acc.x += v0 * a.x; acc.y += v0 * a.y; acc.z += v0 * b.x; acc.w += v0 * b.y;
        }
        {
            float2 a = __half22float2(*reinterpret_cast<__half2*>(&p1.x));
            float2 b = __half22float2(*reinterpret_cast<__half2*>(&p1.y));
            acc.x += v1 * a.x; acc.y += v1 * a.y; acc.z += v1 * b.x; acc.w += v1 * b.y;
        }
        {
            float2 a = __half22float2(*reinterpret_cast<__half2*>(&p2.x));
            float2 b = __half22float2(*reinterpret_cast<__half2*>(&p2.y));
            acc.x += v2 * a.x; acc.y += v2 * a.y; acc.z += v2 * b.x; acc.w += v2 * b.y;
        }
        {
            float2 a = __half22float2(*reinterpret_cast<__half2*>(&p3.x));
            float2 b = __half22float2(*reinterpret_cast<__half2*>(&p3.y));
            acc.x += v3 * a.x; acc.y += v3 * a.y; acc.z += v3 * b.x; acc.w += v3 * b.y;
        }
    }
    for (; e < eend; e++) {
        int2 ed = g_edge[e];
        float v = __int_as_float(ed.y);
        uint2 p = __ldg((const uint2*)(g_support + (size_t)ed.x * AF) + lane);
        float2 a = __half22float2(*reinterpret_cast<__half2*>(&p.x));
        float2 b = __half22float2(*reinterpret_cast<__half2*>(&p.y));
        acc.x += v * a.x; acc.y += v * a.y; acc.z += v * b.x; acc.w += v * b.y;
    }

    ((float4*)(out + (size_t)warp * AF))[lane] = acc;
}

// ---------------------------------------------------------------------------
// Launch: forked-capture parallel branches.
//   main stream : pack -> gemm ----------------+--> spmm
//   side stream : hist -> scan1 -> scan3 -> place
// Event-fork/join is the documented pattern for capturing parallel graph
// branches; it behaves identically (async) in the uncaptured correctness run.
// Stream/event creation is host-side only (no device memory).
// ---------------------------------------------------------------------------
extern "C" void kernel_launch(void* const* d_in, const int* in_sizes, int n_in,
                              void* d_out, int out_size) {
    const float* b_input   = (const float*)d_in[0];
    const int*   edge_rows = (const int*)  d_in[1];
    const int*   edge_cols = (const int*)  d_in[2];
    const float* edge_vals = (const float*)d_in[3];
    const float* a_weight  = (const float*)d_in[4];
    const float* a_bias    = (const float*)d_in[5];
    float*       out       = (float*)d_out;

    cudaStream_t s2;
    cudaStreamCreateWithFlags(&s2, cudaStreamNonBlocking);
    cudaEvent_t ev_fork, ev_join;
    cudaEventCreateWithFlags(&ev_fork, cudaEventDisableTiming);
    cudaEventCreateWithFlags(&ev_join, cudaEventDisableTiming);

    // ---- fork
    cudaEventRecord(ev_fork, 0);
    cudaStreamWaitEvent(s2, ev_fork, 0);

    // ---- main branch: W pack + GEMM
    pack_w_kernel<<<(16 * 16 * 32 + 255) / 256, 256>>>(a_weight);
    gemm_kernel<<<(NB + 127) / 128, 256>>>(b_input);

    // ---- side branch: CSR build
    hist_kernel<<<(NE + 255) / 256, 256, 0, s2>>>(edge_rows);
    scan1_kernel<<<SCAN_NBLK, SCAN_BS, 0, s2>>>();
    scan3_kernel<<<SCAN_NBLK, SCAN_BS, 0, s2>>>();
    place_kernel<<<(NE + 255) / 256, 256, 0, s2>>>(edge_rows, edge_cols, edge_vals);
    cudaEventRecord(ev_join, s2);

    // ---- join, then SpMM (needs g_support + g_edge/g_start)
    cudaStreamWaitEvent(0, ev_join, 0);
    spmm_kernel<<<(NA * 32 + 255) / 256, 256>>>(a_bias, out);
}